// round 10
// baseline (speedup 1.0000x reference)
#include <cuda_runtime.h>
#include <math.h>
#include <stdint.h>

// Problem constants
#define Bb 2
#define LL 2048
#define CC 512
#define HH 8
#define DD 64
#define BL (Bb * LL)   // 4096 rows per input

// Scratch: QKV in [B,H,L,D] per stream s and tensor t (0:Q,1:K,2:V),
// attention outputs in [B,L,C] per stream.
__device__ float g_qkv[2][3][Bb * HH * LL * DD];
__device__ float g_ao[2][BL * CC];

// ---------------------------------------------------------------------------
// tf32 helpers
// ---------------------------------------------------------------------------
__device__ __forceinline__ uint32_t f2tf(float f) {
    uint32_t u;
    asm("cvt.rna.tf32.f32 %0, %1;" : "=r"(u) : "f"(f));
    return u;
}

__device__ __forceinline__ void mma_tf32(float c[4],
                                         uint32_t a0, uint32_t a1, uint32_t a2, uint32_t a3,
                                         uint32_t b0, uint32_t b1) {
    asm volatile(
        "mma.sync.aligned.m16n8k8.row.col.f32.tf32.tf32.f32 "
        "{%0,%1,%2,%3}, {%4,%5,%6,%7}, {%8,%9}, {%0,%1,%2,%3};"
        : "+f"(c[0]), "+f"(c[1]), "+f"(c[2]), "+f"(c[3])
        : "r"(a0), "r"(a1), "r"(a2), "r"(a3), "r"(b0), "r"(b1));
}

// ---------------------------------------------------------------------------
// GEMM kernels (NT): Y[m,n] = sum_k A[m,k] * W[n,k] (+ bias)
// Block tile 128x128, 8 warps, warp tile 32x64 (warps 4m x 2n), k-step 16.
// smem strides: 20 floats per 16-k row (bank-conflict-free fragment loads).
// ---------------------------------------------------------------------------
#define SA 20

struct GemmCore {
    uint32_t (*As)[128 * SA];
    uint32_t (*Bs)[128 * SA];
};

// QKV projection: M=4096 per stream, N=1536, K=512. Scatters to g_qkv.
__global__ __launch_bounds__(256) void qkv_mma(
    const float* __restrict__ x1, const float* __restrict__ x2,
    const float* __restrict__ w, const float* __restrict__ bias)
{
    __shared__ uint32_t As[2][128 * SA];
    __shared__ uint32_t Bs[2][128 * SA];

    const int s  = blockIdx.z;
    const float* __restrict__ X = s ? x2 : x1;
    const int m0 = blockIdx.y * 128;
    const int n0 = blockIdx.x * 128;

    const int tid  = threadIdx.x;
    const int lane = tid & 31;
    const int wid  = tid >> 5;
    const int g = lane >> 2, t = lane & 3;
    const int wm = (wid >> 1) * 32;
    const int wn = (wid & 1) * 64;
    const int lr = tid >> 2;
    const int lc = (tid & 3) * 4;

    const float* __restrict__ Ag = X + (size_t)m0 * CC;
    const float* __restrict__ Bg = w + (size_t)n0 * CC;

    float4 ra0 = *(const float4*)(Ag + (size_t)lr * CC + lc);
    float4 ra1 = *(const float4*)(Ag + (size_t)(lr + 64) * CC + lc);
    float4 rb0 = *(const float4*)(Bg + (size_t)lr * CC + lc);
    float4 rb1 = *(const float4*)(Bg + (size_t)(lr + 64) * CC + lc);

    float acc[2][8][4];
#pragma unroll
    for (int i = 0; i < 2; ++i)
#pragma unroll
        for (int j = 0; j < 8; ++j)
#pragma unroll
            for (int e = 0; e < 4; ++e) acc[i][j][e] = 0.f;

    int buf = 0;
    {
        uint4 u;
        u.x = f2tf(ra0.x); u.y = f2tf(ra0.y); u.z = f2tf(ra0.z); u.w = f2tf(ra0.w);
        *(uint4*)&As[buf][lr * SA + lc] = u;
        u.x = f2tf(ra1.x); u.y = f2tf(ra1.y); u.z = f2tf(ra1.z); u.w = f2tf(ra1.w);
        *(uint4*)&As[buf][(lr + 64) * SA + lc] = u;
        u.x = f2tf(rb0.x); u.y = f2tf(rb0.y); u.z = f2tf(rb0.z); u.w = f2tf(rb0.w);
        *(uint4*)&Bs[buf][lr * SA + lc] = u;
        u.x = f2tf(rb1.x); u.y = f2tf(rb1.y); u.z = f2tf(rb1.z); u.w = f2tf(rb1.w);
        *(uint4*)&Bs[buf][(lr + 64) * SA + lc] = u;
    }
    __syncthreads();

    for (int k0 = 0; k0 < CC; k0 += 16) {
        const bool last = (k0 + 16 >= CC);
        if (!last) {
            ra0 = *(const float4*)(Ag + (size_t)lr * CC + k0 + 16 + lc);
            ra1 = *(const float4*)(Ag + (size_t)(lr + 64) * CC + k0 + 16 + lc);
            rb0 = *(const float4*)(Bg + (size_t)lr * CC + k0 + 16 + lc);
            rb1 = *(const float4*)(Bg + (size_t)(lr + 64) * CC + k0 + 16 + lc);
        }
#pragma unroll
        for (int kk = 0; kk < 2; ++kk) {
            uint32_t a[2][4];
#pragma unroll
            for (int mf = 0; mf < 2; ++mf) {
                const int row = wm + mf * 16;
                a[mf][0] = As[buf][(row + g) * SA + kk * 8 + t];
                a[mf][1] = As[buf][(row + g + 8) * SA + kk * 8 + t];
                a[mf][2] = As[buf][(row + g) * SA + kk * 8 + t + 4];
                a[mf][3] = As[buf][(row + g + 8) * SA + kk * 8 + t + 4];
            }
#pragma unroll
            for (int nf = 0; nf < 8; ++nf) {
                const int col = wn + nf * 8;
                uint32_t b0 = Bs[buf][(col + g) * SA + kk * 8 + t];
                uint32_t b1 = Bs[buf][(col + g) * SA + kk * 8 + t + 4];
                mma_tf32(acc[0][nf], a[0][0], a[0][1], a[0][2], a[0][3], b0, b1);
                mma_tf32(acc[1][nf], a[1][0], a[1][1], a[1][2], a[1][3], b0, b1);
            }
        }
        if (!last) {
            const int nb = buf ^ 1;
            uint4 u;
            u.x = f2tf(ra0.x); u.y = f2tf(ra0.y); u.z = f2tf(ra0.z); u.w = f2tf(ra0.w);
            *(uint4*)&As[nb][lr * SA + lc] = u;
            u.x = f2tf(ra1.x); u.y = f2tf(ra1.y); u.z = f2tf(ra1.z); u.w = f2tf(ra1.w);
            *(uint4*)&As[nb][(lr + 64) * SA + lc] = u;
            u.x = f2tf(rb0.x); u.y = f2tf(rb0.y); u.z = f2tf(rb0.z); u.w = f2tf(rb0.w);
            *(uint4*)&Bs[nb][lr * SA + lc] = u;
            u.x = f2tf(rb1.x); u.y = f2tf(rb1.y); u.z = f2tf(rb1.z); u.w = f2tf(rb1.w);
            *(uint4*)&Bs[nb][(lr + 64) * SA + lc] = u;
            __syncthreads();
            buf = nb;
        }
    }

    // Epilogue: scatter into g_qkv
#pragma unroll
    for (int mf = 0; mf < 2; ++mf) {
        const int mA = m0 + wm + mf * 16 + g;
        const int mB = mA + 8;
#pragma unroll
        for (int nf = 0; nf < 8; ++nf) {
            const int f   = n0 + wn + nf * 8 + 2 * t;
            const int h   = f / 192;
            const int rem = f % 192;
            const int tsr = rem / 64;
            const int d   = rem & 63;
            const float bv0 = bias[f], bv1 = bias[f + 1];
            {
                const int bb = mA >> 11, l = mA & 2047;
                float2 v = make_float2(acc[mf][nf][0] + bv0, acc[mf][nf][1] + bv1);
                *(float2*)&g_qkv[s][tsr][(size_t)((bb * HH + h) * LL + l) * DD + d] = v;
            }
            {
                const int bb = mB >> 11, l = mB & 2047;
                float2 v = make_float2(acc[mf][nf][2] + bv0, acc[mf][nf][3] + bv1);
                *(float2*)&g_qkv[s][tsr][(size_t)((bb * HH + h) * LL + l) * DD + d] = v;
            }
        }
    }
}

// Output projection: M=8192, N=512, K=512. Reads g_ao, writes d_out.
__global__ __launch_bounds__(256) void proj_mma(
    const float* __restrict__ w, const float* __restrict__ bias,
    float* __restrict__ out)
{
    __shared__ uint32_t As[2][128 * SA];
    __shared__ uint32_t Bs[2][128 * SA];

    const int m0 = blockIdx.y * 128;
    const int n0 = blockIdx.x * 128;
    const float* __restrict__ A = &g_ao[0][0];

    const int tid  = threadIdx.x;
    const int lane = tid & 31;
    const int wid  = tid >> 5;
    const int g = lane >> 2, t = lane & 3;
    const int wm = (wid >> 1) * 32;
    const int wn = (wid & 1) * 64;
    const int lr = tid >> 2;
    const int lc = (tid & 3) * 4;

    const float* __restrict__ Ag = A + (size_t)m0 * CC;
    const float* __restrict__ Bg = w + (size_t)n0 * CC;

    float4 ra0 = *(const float4*)(Ag + (size_t)lr * CC + lc);
    float4 ra1 = *(const float4*)(Ag + (size_t)(lr + 64) * CC + lc);
    float4 rb0 = *(const float4*)(Bg + (size_t)lr * CC + lc);
    float4 rb1 = *(const float4*)(Bg + (size_t)(lr + 64) * CC + lc);

    float acc[2][8][4];
#pragma unroll
    for (int i = 0; i < 2; ++i)
#pragma unroll
        for (int j = 0; j < 8; ++j)
#pragma unroll
            for (int e = 0; e < 4; ++e) acc[i][j][e] = 0.f;

    int buf = 0;
    {
        uint4 u;
        u.x = f2tf(ra0.x); u.y = f2tf(ra0.y); u.z = f2tf(ra0.z); u.w = f2tf(ra0.w);
        *(uint4*)&As[buf][lr * SA + lc] = u;
        u.x = f2tf(ra1.x); u.y = f2tf(ra1.y); u.z = f2tf(ra1.z); u.w = f2tf(ra1.w);
        *(uint4*)&As[buf][(lr + 64) * SA + lc] = u;
        u.x = f2tf(rb0.x); u.y = f2tf(rb0.y); u.z = f2tf(rb0.z); u.w = f2tf(rb0.w);
        *(uint4*)&Bs[buf][lr * SA + lc] = u;
        u.x = f2tf(rb1.x); u.y = f2tf(rb1.y); u.z = f2tf(rb1.z); u.w = f2tf(rb1.w);
        *(uint4*)&Bs[buf][(lr + 64) * SA + lc] = u;
    }
    __syncthreads();

    for (int k0 = 0; k0 < CC; k0 += 16) {
        const bool last = (k0 + 16 >= CC);
        if (!last) {
            ra0 = *(const float4*)(Ag + (size_t)lr * CC + k0 + 16 + lc);
            ra1 = *(const float4*)(Ag + (size_t)(lr + 64) * CC + k0 + 16 + lc);
            rb0 = *(const float4*)(Bg + (size_t)lr * CC + k0 + 16 + lc);
            rb1 = *(const float4*)(Bg + (size_t)(lr + 64) * CC + k0 + 16 + lc);
        }
#pragma unroll
        for (int kk = 0; kk < 2; ++kk) {
            uint32_t a[2][4];
#pragma unroll
            for (int mf = 0; mf < 2; ++mf) {
                const int row = wm + mf * 16;
                a[mf][0] = As[buf][(row + g) * SA + kk * 8 + t];
                a[mf][1] = As[buf][(row + g + 8) * SA + kk * 8 + t];
                a[mf][2] = As[buf][(row + g) * SA + kk * 8 + t + 4];
                a[mf][3] = As[buf][(row + g + 8) * SA + kk * 8 + t + 4];
            }
#pragma unroll
            for (int nf = 0; nf < 8; ++nf) {
                const int col = wn + nf * 8;
                uint32_t b0 = Bs[buf][(col + g) * SA + kk * 8 + t];
                uint32_t b1 = Bs[buf][(col + g) * SA + kk * 8 + t + 4];
                mma_tf32(acc[0][nf], a[0][0], a[0][1], a[0][2], a[0][3], b0, b1);
                mma_tf32(acc[1][nf], a[1][0], a[1][1], a[1][2], a[1][3], b0, b1);
            }
        }
        if (!last) {
            const int nb = buf ^ 1;
            uint4 u;
            u.x = f2tf(ra0.x); u.y = f2tf(ra0.y); u.z = f2tf(ra0.z); u.w = f2tf(ra0.w);
            *(uint4*)&As[nb][lr * SA + lc] = u;
            u.x = f2tf(ra1.x); u.y = f2tf(ra1.y); u.z = f2tf(ra1.z); u.w = f2tf(ra1.w);
            *(uint4*)&As[nb][(lr + 64) * SA + lc] = u;
            u.x = f2tf(rb0.x); u.y = f2tf(rb0.y); u.z = f2tf(rb0.z); u.w = f2tf(rb0.w);
            *(uint4*)&Bs[nb][lr * SA + lc] = u;
            u.x = f2tf(rb1.x); u.y = f2tf(rb1.y); u.z = f2tf(rb1.z); u.w = f2tf(rb1.w);
            *(uint4*)&Bs[nb][(lr + 64) * SA + lc] = u;
            __syncthreads();
            buf = nb;
        }
    }

#pragma unroll
    for (int mf = 0; mf < 2; ++mf) {
        const int mA = m0 + wm + mf * 16 + g;
        const int mB = mA + 8;
#pragma unroll
        for (int nf = 0; nf < 8; ++nf) {
            const int n = n0 + wn + nf * 8 + 2 * t;
            const float bv0 = bias[n], bv1 = bias[n + 1];
            float2 vA = make_float2(acc[mf][nf][0] + bv0, acc[mf][nf][1] + bv1);
            float2 vB = make_float2(acc[mf][nf][2] + bv0, acc[mf][nf][3] + bv1);
            *(float2*)&out[(size_t)mA * CC + n] = vA;
            *(float2*)&out[(size_t)mB * CC + n] = vB;
        }
    }
}

// ---------------------------------------------------------------------------
// Flash attention with tf32 mma.
// Block: 128 threads (4 warps), q-tile 64, kv-tile 64, D=64.
// Warp owns 16 q rows x full 64 kv cols (no cross-warp softmax reduction).
// smem: KP (K tile, reused for P) + Vs, both tf32, stride 68.
// ---------------------------------------------------------------------------
#define SV 68

__global__ __launch_bounds__(128) void attn_mma()
{
    __shared__ uint32_t KP[64 * SV];
    __shared__ uint32_t Vs[64 * SV];

    const int s  = blockIdx.z;
    const int bh = blockIdx.y;
    const int q0 = blockIdx.x * 64;

    const float* __restrict__ Qg = &g_qkv[s][0][(size_t)bh * LL * DD];
    const float* __restrict__ Kg = &g_qkv[1 - s][1][(size_t)bh * LL * DD];
    const float* __restrict__ Vg = &g_qkv[1 - s][2][(size_t)bh * LL * DD];

    const int tid  = threadIdx.x;
    const int lane = tid & 31;
    const int wid  = tid >> 5;
    const int g = lane >> 2, t = lane & 3;
    const int wr = wid * 16;

    const int lrr = tid >> 1;          // 0..63 (row)
    const int lh  = tid & 1;           // column half selector

    // Stage Q (prescaled) into Vs, pull Q fragments into registers.
#pragma unroll
    for (int j = 0; j < 8; ++j) {
        const int c4 = (lh + 2 * j) * 4;
        float4 q = *(const float4*)(Qg + (size_t)(q0 + lrr) * DD + c4);
        uint4 u;
        u.x = f2tf(q.x * 0.125f); u.y = f2tf(q.y * 0.125f);
        u.z = f2tf(q.z * 0.125f); u.w = f2tf(q.w * 0.125f);
        *(uint4*)&Vs[lrr * SV + c4] = u;
    }
    __syncthreads();

    uint32_t qa[8][4];
#pragma unroll
    for (int kk = 0; kk < 8; ++kk) {
        qa[kk][0] = Vs[(wr + g) * SV + kk * 8 + t];
        qa[kk][1] = Vs[(wr + g + 8) * SV + kk * 8 + t];
        qa[kk][2] = Vs[(wr + g) * SV + kk * 8 + t + 4];
        qa[kk][3] = Vs[(wr + g + 8) * SV + kk * 8 + t + 4];
    }
    __syncthreads();

    float o[8][4];
#pragma unroll
    for (int nf = 0; nf < 8; ++nf)
#pragma unroll
        for (int e = 0; e < 4; ++e) o[nf][e] = 0.f;
    float mrow0 = -INFINITY, mrow1 = -INFINITY;
    float lrow0 = 0.f, lrow1 = 0.f;

    for (int kt = 0; kt < LL; kt += 64) {
        // Load K -> KP, V -> Vs (tf32)
#pragma unroll
        for (int j = 0; j < 8; ++j) {
            const int c4 = (lh + 2 * j) * 4;
            float4 kv = *(const float4*)(Kg + (size_t)(kt + lrr) * DD + c4);
            uint4 u;
            u.x = f2tf(kv.x); u.y = f2tf(kv.y); u.z = f2tf(kv.z); u.w = f2tf(kv.w);
            *(uint4*)&KP[lrr * SV + c4] = u;
            float4 vv = *(const float4*)(Vg + (size_t)(kt + lrr) * DD + c4);
            u.x = f2tf(vv.x); u.y = f2tf(vv.y); u.z = f2tf(vv.z); u.w = f2tf(vv.w);
            *(uint4*)&Vs[lrr * SV + c4] = u;
        }
        __syncthreads();

        // S = Q @ K^T  (warp: 16 x 64)
        float sc[8][4];
#pragma unroll
        for (int nf = 0; nf < 8; ++nf)
#pragma unroll
            for (int e = 0; e < 4; ++e) sc[nf][e] = 0.f;
#pragma unroll
        for (int nf = 0; nf < 8; ++nf) {
#pragma unroll
            for (int kk = 0; kk < 8; ++kk) {
                uint32_t b0 = KP[(nf * 8 + g) * SV + kk * 8 + t];
                uint32_t b1 = KP[(nf * 8 + g) * SV + kk * 8 + t + 4];
                mma_tf32(sc[nf], qa[kk][0], qa[kk][1], qa[kk][2], qa[kk][3], b0, b1);
            }
        }

        // Online softmax (rows g and g+8 of warp tile; lanes sharing g = t-quad)
        float mx0 = -INFINITY, mx1 = -INFINITY;
#pragma unroll
        for (int nf = 0; nf < 8; ++nf) {
            mx0 = fmaxf(mx0, fmaxf(sc[nf][0], sc[nf][1]));
            mx1 = fmaxf(mx1, fmaxf(sc[nf][2], sc[nf][3]));
        }
        mx0 = fmaxf(mx0, __shfl_xor_sync(0xffffffffu, mx0, 1));
        mx0 = fmaxf(mx0, __shfl_xor_sync(0xffffffffu, mx0, 2));
        mx1 = fmaxf(mx1, __shfl_xor_sync(0xffffffffu, mx1, 1));
        mx1 = fmaxf(mx1, __shfl_xor_sync(0xffffffffu, mx1, 2));

        const float mn0 = fmaxf(mrow0, mx0);
        const float mn1 = fmaxf(mrow1, mx1);
        const float corr0 = __expf(mrow0 - mn0);
        const float corr1 = __expf(mrow1 - mn1);
        mrow0 = mn0; mrow1 = mn1;

        float ls0 = 0.f, ls1 = 0.f;
#pragma unroll
        for (int nf = 0; nf < 8; ++nf) {
            sc[nf][0] = __expf(sc[nf][0] - mn0); ls0 += sc[nf][0];
            sc[nf][1] = __expf(sc[nf][1] - mn0); ls0 += sc[nf][1];
            sc[nf][2] = __expf(sc[nf][2] - mn1); ls1 += sc[nf][2];
            sc[nf][3] = __expf(sc[nf][3] - mn1); ls1 += sc[nf][3];
        }
        ls0 += __shfl_xor_sync(0xffffffffu, ls0, 1);
        ls0 += __shfl_xor_sync(0xffffffffu, ls0, 2);
        ls1 += __shfl_xor_sync(0xffffffffu, ls1, 1);
        ls1 += __shfl_xor_sync(0xffffffffu, ls1, 2);
        lrow0 = lrow0 * corr0 + ls0;
        lrow1 = lrow1 * corr1 + ls1;
#pragma unroll
        for (int nf = 0; nf < 8; ++nf) {
            o[nf][0] *= corr0; o[nf][1] *= corr0;
            o[nf][2] *= corr1; o[nf][3] *= corr1;
        }

        __syncthreads();   // all warps done reading KP as K

        // Store P (tf32) into KP; each warp only touches its own 16 rows.
#pragma unroll
        for (int nf = 0; nf < 8; ++nf) {
            uint2 uA, uB;
            uA.x = f2tf(sc[nf][0]); uA.y = f2tf(sc[nf][1]);
            uB.x = f2tf(sc[nf][2]); uB.y = f2tf(sc[nf][3]);
            *(uint2*)&KP[(wr + g) * SV + nf * 8 + 2 * t] = uA;
            *(uint2*)&KP[(wr + g + 8) * SV + nf * 8 + 2 * t] = uB;
        }
        __syncwarp();

        // O += P @ V
#pragma unroll
        for (int kk = 0; kk < 8; ++kk) {
            uint32_t p0 = KP[(wr + g) * SV + kk * 8 + t];
            uint32_t p1 = KP[(wr + g + 8) * SV + kk * 8 + t];
            uint32_t p2 = KP[(wr + g) * SV + kk * 8 + t + 4];
            uint32_t p3 = KP[(wr + g + 8) * SV + kk * 8 + t + 4];
#pragma unroll
            for (int nf = 0; nf < 8; ++nf) {
                uint32_t b0 = Vs[(kk * 8 + t) * SV + nf * 8 + g];
                uint32_t b1 = Vs[(kk * 8 + t + 4) * SV + nf * 8 + g];
                mma_tf32(o[nf], p0, p1, p2, p3, b0, b1);
            }
        }
        __syncthreads();   // before next tile overwrites KP/Vs
    }

    // Epilogue: normalize, write to g_ao[s] in [B, L, H*D]
    const int bb = bh >> 3;
    const int h  = bh & 7;
    const float inv0 = 1.f / lrow0;
    const float inv1 = 1.f / lrow1;
    const int rowA = q0 + wr + g;
    const int rowB = rowA + 8;
    float* __restrict__ ao = &g_ao[s][0];
#pragma unroll
    for (int nf = 0; nf < 8; ++nf) {
        const int col = h * DD + nf * 8 + 2 * t;
        float2 vA = make_float2(o[nf][0] * inv0, o[nf][1] * inv0);
        float2 vB = make_float2(o[nf][2] * inv1, o[nf][3] * inv1);
        *(float2*)&ao[(size_t)(bb * LL + rowA) * CC + col] = vA;
        *(float2*)&ao[(size_t)(bb * LL + rowB) * CC + col] = vB;
    }
}

// ---------------------------------------------------------------------------
extern "C" void kernel_launch(void* const* d_in, const int* in_sizes, int n_in,
                              void* d_out, int out_size)
{
    const float* x1    = (const float*)d_in[0];
    const float* x2    = (const float*)d_in[1];
    const float* qkv_w = (const float*)d_in[2];
    const float* qkv_b = (const float*)d_in[3];
    const float* out_w = (const float*)d_in[4];
    const float* out_b = (const float*)d_in[5];
    float* out = (float*)d_out;

    // Stage 1: QKV projections (both inputs)
    qkv_mma<<<dim3(1536 / 128, BL / 128, 2), 256>>>(x1, x2, qkv_w, qkv_b);

    // Stage 2: cross attention (both directions)
    attn_mma<<<dim3(LL / 64, Bb * HH, 2), 128>>>();

    // Stage 3: output projection -> d_out (out1 then out2)
    proj_mma<<<dim3(CC / 128, 2 * BL / 128), 256>>>(out_w, out_b, out);
}

// round 11
// speedup vs baseline: 1.0010x; 1.0010x over previous
#include <cuda_runtime.h>
#include <math.h>
#include <stdint.h>

// Problem constants
#define Bb 2
#define LL 2048
#define CC 512
#define HH 8
#define DD 64
#define BL (Bb * LL)   // 4096 rows per input

// Scratch: QKV in [B,H,L,D] per stream s and tensor t (0:Q,1:K,2:V),
// attention outputs in [B,L,C] per stream.
__device__ float g_qkv[2][3][Bb * HH * LL * DD];
__device__ float g_ao[2][BL * CC];

// ---------------------------------------------------------------------------
// tf32 helpers
// ---------------------------------------------------------------------------
__device__ __forceinline__ uint32_t f2tf(float f) {
    uint32_t u;
    asm("cvt.rna.tf32.f32 %0, %1;" : "=r"(u) : "f"(f));
    return u;
}

__device__ __forceinline__ void mma_tf32(float c[4],
                                         uint32_t a0, uint32_t a1, uint32_t a2, uint32_t a3,
                                         uint32_t b0, uint32_t b1) {
    asm volatile(
        "mma.sync.aligned.m16n8k8.row.col.f32.tf32.tf32.f32 "
        "{%0,%1,%2,%3}, {%4,%5,%6,%7}, {%8,%9}, {%0,%1,%2,%3};"
        : "+f"(c[0]), "+f"(c[1]), "+f"(c[2]), "+f"(c[3])
        : "r"(a0), "r"(a1), "r"(a2), "r"(a3), "r"(b0), "r"(b1));
}

// ---------------------------------------------------------------------------
// GEMM kernels (NT): Y[m,n] = sum_k A[m,k] * W[n,k] (+ bias)
// Block tile 128x128, 8 warps, warp tile 32x64 (warps 4m x 2n), k-step 16.
// smem strides: 20 floats per 16-k row (bank-conflict-free fragment loads).
// ---------------------------------------------------------------------------
#define SA 20

struct GemmCore {
    uint32_t (*As)[128 * SA];
    uint32_t (*Bs)[128 * SA];
};

// QKV projection: M=4096 per stream, N=1536, K=512. Scatters to g_qkv.
__global__ __launch_bounds__(256) void qkv_mma(
    const float* __restrict__ x1, const float* __restrict__ x2,
    const float* __restrict__ w, const float* __restrict__ bias)
{
    __shared__ uint32_t As[2][128 * SA];
    __shared__ uint32_t Bs[2][128 * SA];

    const int s  = blockIdx.z;
    const float* __restrict__ X = s ? x2 : x1;
    const int m0 = blockIdx.y * 128;
    const int n0 = blockIdx.x * 128;

    const int tid  = threadIdx.x;
    const int lane = tid & 31;
    const int wid  = tid >> 5;
    const int g = lane >> 2, t = lane & 3;
    const int wm = (wid >> 1) * 32;
    const int wn = (wid & 1) * 64;
    const int lr = tid >> 2;
    const int lc = (tid & 3) * 4;

    const float* __restrict__ Ag = X + (size_t)m0 * CC;
    const float* __restrict__ Bg = w + (size_t)n0 * CC;

    float4 ra0 = *(const float4*)(Ag + (size_t)lr * CC + lc);
    float4 ra1 = *(const float4*)(Ag + (size_t)(lr + 64) * CC + lc);
    float4 rb0 = *(const float4*)(Bg + (size_t)lr * CC + lc);
    float4 rb1 = *(const float4*)(Bg + (size_t)(lr + 64) * CC + lc);

    float acc[2][8][4];
#pragma unroll
    for (int i = 0; i < 2; ++i)
#pragma unroll
        for (int j = 0; j < 8; ++j)
#pragma unroll
            for (int e = 0; e < 4; ++e) acc[i][j][e] = 0.f;

    int buf = 0;
    {
        uint4 u;
        u.x = f2tf(ra0.x); u.y = f2tf(ra0.y); u.z = f2tf(ra0.z); u.w = f2tf(ra0.w);
        *(uint4*)&As[buf][lr * SA + lc] = u;
        u.x = f2tf(ra1.x); u.y = f2tf(ra1.y); u.z = f2tf(ra1.z); u.w = f2tf(ra1.w);
        *(uint4*)&As[buf][(lr + 64) * SA + lc] = u;
        u.x = f2tf(rb0.x); u.y = f2tf(rb0.y); u.z = f2tf(rb0.z); u.w = f2tf(rb0.w);
        *(uint4*)&Bs[buf][lr * SA + lc] = u;
        u.x = f2tf(rb1.x); u.y = f2tf(rb1.y); u.z = f2tf(rb1.z); u.w = f2tf(rb1.w);
        *(uint4*)&Bs[buf][(lr + 64) * SA + lc] = u;
    }
    __syncthreads();

    for (int k0 = 0; k0 < CC; k0 += 16) {
        const bool last = (k0 + 16 >= CC);
        if (!last) {
            ra0 = *(const float4*)(Ag + (size_t)lr * CC + k0 + 16 + lc);
            ra1 = *(const float4*)(Ag + (size_t)(lr + 64) * CC + k0 + 16 + lc);
            rb0 = *(const float4*)(Bg + (size_t)lr * CC + k0 + 16 + lc);
            rb1 = *(const float4*)(Bg + (size_t)(lr + 64) * CC + k0 + 16 + lc);
        }
#pragma unroll
        for (int kk = 0; kk < 2; ++kk) {
            uint32_t a[2][4];
#pragma unroll
            for (int mf = 0; mf < 2; ++mf) {
                const int row = wm + mf * 16;
                a[mf][0] = As[buf][(row + g) * SA + kk * 8 + t];
                a[mf][1] = As[buf][(row + g + 8) * SA + kk * 8 + t];
                a[mf][2] = As[buf][(row + g) * SA + kk * 8 + t + 4];
                a[mf][3] = As[buf][(row + g + 8) * SA + kk * 8 + t + 4];
            }
#pragma unroll
            for (int nf = 0; nf < 8; ++nf) {
                const int col = wn + nf * 8;
                uint32_t b0 = Bs[buf][(col + g) * SA + kk * 8 + t];
                uint32_t b1 = Bs[buf][(col + g) * SA + kk * 8 + t + 4];
                mma_tf32(acc[0][nf], a[0][0], a[0][1], a[0][2], a[0][3], b0, b1);
                mma_tf32(acc[1][nf], a[1][0], a[1][1], a[1][2], a[1][3], b0, b1);
            }
        }
        if (!last) {
            const int nb = buf ^ 1;
            uint4 u;
            u.x = f2tf(ra0.x); u.y = f2tf(ra0.y); u.z = f2tf(ra0.z); u.w = f2tf(ra0.w);
            *(uint4*)&As[nb][lr * SA + lc] = u;
            u.x = f2tf(ra1.x); u.y = f2tf(ra1.y); u.z = f2tf(ra1.z); u.w = f2tf(ra1.w);
            *(uint4*)&As[nb][(lr + 64) * SA + lc] = u;
            u.x = f2tf(rb0.x); u.y = f2tf(rb0.y); u.z = f2tf(rb0.z); u.w = f2tf(rb0.w);
            *(uint4*)&Bs[nb][lr * SA + lc] = u;
            u.x = f2tf(rb1.x); u.y = f2tf(rb1.y); u.z = f2tf(rb1.z); u.w = f2tf(rb1.w);
            *(uint4*)&Bs[nb][(lr + 64) * SA + lc] = u;
            __syncthreads();
            buf = nb;
        }
    }

    // Epilogue: scatter into g_qkv
#pragma unroll
    for (int mf = 0; mf < 2; ++mf) {
        const int mA = m0 + wm + mf * 16 + g;
        const int mB = mA + 8;
#pragma unroll
        for (int nf = 0; nf < 8; ++nf) {
            const int f   = n0 + wn + nf * 8 + 2 * t;
            const int h   = f / 192;
            const int rem = f % 192;
            const int tsr = rem / 64;
            const int d   = rem & 63;
            const float bv0 = bias[f], bv1 = bias[f + 1];
            {
                const int bb = mA >> 11, l = mA & 2047;
                float2 v = make_float2(acc[mf][nf][0] + bv0, acc[mf][nf][1] + bv1);
                *(float2*)&g_qkv[s][tsr][(size_t)((bb * HH + h) * LL + l) * DD + d] = v;
            }
            {
                const int bb = mB >> 11, l = mB & 2047;
                float2 v = make_float2(acc[mf][nf][2] + bv0, acc[mf][nf][3] + bv1);
                *(float2*)&g_qkv[s][tsr][(size_t)((bb * HH + h) * LL + l) * DD + d] = v;
            }
        }
    }
}

// Output projection: M=8192, N=512, K=512. Reads g_ao, writes d_out.
__global__ __launch_bounds__(256) void proj_mma(
    const float* __restrict__ w, const float* __restrict__ bias,
    float* __restrict__ out)
{
    __shared__ uint32_t As[2][128 * SA];
    __shared__ uint32_t Bs[2][128 * SA];

    const int m0 = blockIdx.y * 128;
    const int n0 = blockIdx.x * 128;
    const float* __restrict__ A = &g_ao[0][0];

    const int tid  = threadIdx.x;
    const int lane = tid & 31;
    const int wid  = tid >> 5;
    const int g = lane >> 2, t = lane & 3;
    const int wm = (wid >> 1) * 32;
    const int wn = (wid & 1) * 64;
    const int lr = tid >> 2;
    const int lc = (tid & 3) * 4;

    const float* __restrict__ Ag = A + (size_t)m0 * CC;
    const float* __restrict__ Bg = w + (size_t)n0 * CC;

    float4 ra0 = *(const float4*)(Ag + (size_t)lr * CC + lc);
    float4 ra1 = *(const float4*)(Ag + (size_t)(lr + 64) * CC + lc);
    float4 rb0 = *(const float4*)(Bg + (size_t)lr * CC + lc);
    float4 rb1 = *(const float4*)(Bg + (size_t)(lr + 64) * CC + lc);

    float acc[2][8][4];
#pragma unroll
    for (int i = 0; i < 2; ++i)
#pragma unroll
        for (int j = 0; j < 8; ++j)
#pragma unroll
            for (int e = 0; e < 4; ++e) acc[i][j][e] = 0.f;

    int buf = 0;
    {
        uint4 u;
        u.x = f2tf(ra0.x); u.y = f2tf(ra0.y); u.z = f2tf(ra0.z); u.w = f2tf(ra0.w);
        *(uint4*)&As[buf][lr * SA + lc] = u;
        u.x = f2tf(ra1.x); u.y = f2tf(ra1.y); u.z = f2tf(ra1.z); u.w = f2tf(ra1.w);
        *(uint4*)&As[buf][(lr + 64) * SA + lc] = u;
        u.x = f2tf(rb0.x); u.y = f2tf(rb0.y); u.z = f2tf(rb0.z); u.w = f2tf(rb0.w);
        *(uint4*)&Bs[buf][lr * SA + lc] = u;
        u.x = f2tf(rb1.x); u.y = f2tf(rb1.y); u.z = f2tf(rb1.z); u.w = f2tf(rb1.w);
        *(uint4*)&Bs[buf][(lr + 64) * SA + lc] = u;
    }
    __syncthreads();

    for (int k0 = 0; k0 < CC; k0 += 16) {
        const bool last = (k0 + 16 >= CC);
        if (!last) {
            ra0 = *(const float4*)(Ag + (size_t)lr * CC + k0 + 16 + lc);
            ra1 = *(const float4*)(Ag + (size_t)(lr + 64) * CC + k0 + 16 + lc);
            rb0 = *(const float4*)(Bg + (size_t)lr * CC + k0 + 16 + lc);
            rb1 = *(const float4*)(Bg + (size_t)(lr + 64) * CC + k0 + 16 + lc);
        }
#pragma unroll
        for (int kk = 0; kk < 2; ++kk) {
            uint32_t a[2][4];
#pragma unroll
            for (int mf = 0; mf < 2; ++mf) {
                const int row = wm + mf * 16;
                a[mf][0] = As[buf][(row + g) * SA + kk * 8 + t];
                a[mf][1] = As[buf][(row + g + 8) * SA + kk * 8 + t];
                a[mf][2] = As[buf][(row + g) * SA + kk * 8 + t + 4];
                a[mf][3] = As[buf][(row + g + 8) * SA + kk * 8 + t + 4];
            }
#pragma unroll
            for (int nf = 0; nf < 8; ++nf) {
                const int col = wn + nf * 8;
                uint32_t b0 = Bs[buf][(col + g) * SA + kk * 8 + t];
                uint32_t b1 = Bs[buf][(col + g) * SA + kk * 8 + t + 4];
                mma_tf32(acc[0][nf], a[0][0], a[0][1], a[0][2], a[0][3], b0, b1);
                mma_tf32(acc[1][nf], a[1][0], a[1][1], a[1][2], a[1][3], b0, b1);
            }
        }
        if (!last) {
            const int nb = buf ^ 1;
            uint4 u;
            u.x = f2tf(ra0.x); u.y = f2tf(ra0.y); u.z = f2tf(ra0.z); u.w = f2tf(ra0.w);
            *(uint4*)&As[nb][lr * SA + lc] = u;
            u.x = f2tf(ra1.x); u.y = f2tf(ra1.y); u.z = f2tf(ra1.z); u.w = f2tf(ra1.w);
            *(uint4*)&As[nb][(lr + 64) * SA + lc] = u;
            u.x = f2tf(rb0.x); u.y = f2tf(rb0.y); u.z = f2tf(rb0.z); u.w = f2tf(rb0.w);
            *(uint4*)&Bs[nb][lr * SA + lc] = u;
            u.x = f2tf(rb1.x); u.y = f2tf(rb1.y); u.z = f2tf(rb1.z); u.w = f2tf(rb1.w);
            *(uint4*)&Bs[nb][(lr + 64) * SA + lc] = u;
            __syncthreads();
            buf = nb;
        }
    }

#pragma unroll
    for (int mf = 0; mf < 2; ++mf) {
        const int mA = m0 + wm + mf * 16 + g;
        const int mB = mA + 8;
#pragma unroll
        for (int nf = 0; nf < 8; ++nf) {
            const int n = n0 + wn + nf * 8 + 2 * t;
            const float bv0 = bias[n], bv1 = bias[n + 1];
            float2 vA = make_float2(acc[mf][nf][0] + bv0, acc[mf][nf][1] + bv1);
            float2 vB = make_float2(acc[mf][nf][2] + bv0, acc[mf][nf][3] + bv1);
            *(float2*)&out[(size_t)mA * CC + n] = vA;
            *(float2*)&out[(size_t)mB * CC + n] = vB;
        }
    }
}

// ---------------------------------------------------------------------------
// Flash attention with tf32 mma.
// Block: 128 threads (4 warps), q-tile 64, kv-tile 64, D=64.
// Warp owns 16 q rows x full 64 kv cols (no cross-warp softmax reduction).
// smem: KP (K tile, reused for P) + Vs, both tf32, stride 68.
// ---------------------------------------------------------------------------
#define SV 68

__global__ __launch_bounds__(128) void attn_mma()
{
    __shared__ uint32_t KP[64 * SV];
    __shared__ uint32_t Vs[64 * SV];

    const int s  = blockIdx.z;
    const int bh = blockIdx.y;
    const int q0 = blockIdx.x * 64;

    const float* __restrict__ Qg = &g_qkv[s][0][(size_t)bh * LL * DD];
    const float* __restrict__ Kg = &g_qkv[1 - s][1][(size_t)bh * LL * DD];
    const float* __restrict__ Vg = &g_qkv[1 - s][2][(size_t)bh * LL * DD];

    const int tid  = threadIdx.x;
    const int lane = tid & 31;
    const int wid  = tid >> 5;
    const int g = lane >> 2, t = lane & 3;
    const int wr = wid * 16;

    const int lrr = tid >> 1;          // 0..63 (row)
    const int lh  = tid & 1;           // column half selector

    // Stage Q (prescaled) into Vs, pull Q fragments into registers.
#pragma unroll
    for (int j = 0; j < 8; ++j) {
        const int c4 = (lh + 2 * j) * 4;
        float4 q = *(const float4*)(Qg + (size_t)(q0 + lrr) * DD + c4);
        uint4 u;
        u.x = f2tf(q.x * 0.125f); u.y = f2tf(q.y * 0.125f);
        u.z = f2tf(q.z * 0.125f); u.w = f2tf(q.w * 0.125f);
        *(uint4*)&Vs[lrr * SV + c4] = u;
    }
    __syncthreads();

    uint32_t qa[8][4];
#pragma unroll
    for (int kk = 0; kk < 8; ++kk) {
        qa[kk][0] = Vs[(wr + g) * SV + kk * 8 + t];
        qa[kk][1] = Vs[(wr + g + 8) * SV + kk * 8 + t];
        qa[kk][2] = Vs[(wr + g) * SV + kk * 8 + t + 4];
        qa[kk][3] = Vs[(wr + g + 8) * SV + kk * 8 + t + 4];
    }
    __syncthreads();

    float o[8][4];
#pragma unroll
    for (int nf = 0; nf < 8; ++nf)
#pragma unroll
        for (int e = 0; e < 4; ++e) o[nf][e] = 0.f;
    float mrow0 = -INFINITY, mrow1 = -INFINITY;
    float lrow0 = 0.f, lrow1 = 0.f;

    for (int kt = 0; kt < LL; kt += 64) {
        // Load K -> KP, V -> Vs (tf32)
#pragma unroll
        for (int j = 0; j < 8; ++j) {
            const int c4 = (lh + 2 * j) * 4;
            float4 kv = *(const float4*)(Kg + (size_t)(kt + lrr) * DD + c4);
            uint4 u;
            u.x = f2tf(kv.x); u.y = f2tf(kv.y); u.z = f2tf(kv.z); u.w = f2tf(kv.w);
            *(uint4*)&KP[lrr * SV + c4] = u;
            float4 vv = *(const float4*)(Vg + (size_t)(kt + lrr) * DD + c4);
            u.x = f2tf(vv.x); u.y = f2tf(vv.y); u.z = f2tf(vv.z); u.w = f2tf(vv.w);
            *(uint4*)&Vs[lrr * SV + c4] = u;
        }
        __syncthreads();

        // S = Q @ K^T  (warp: 16 x 64)
        float sc[8][4];
#pragma unroll
        for (int nf = 0; nf < 8; ++nf)
#pragma unroll
            for (int e = 0; e < 4; ++e) sc[nf][e] = 0.f;
#pragma unroll
        for (int nf = 0; nf < 8; ++nf) {
#pragma unroll
            for (int kk = 0; kk < 8; ++kk) {
                uint32_t b0 = KP[(nf * 8 + g) * SV + kk * 8 + t];
                uint32_t b1 = KP[(nf * 8 + g) * SV + kk * 8 + t + 4];
                mma_tf32(sc[nf], qa[kk][0], qa[kk][1], qa[kk][2], qa[kk][3], b0, b1);
            }
        }

        // Online softmax (rows g and g+8 of warp tile; lanes sharing g = t-quad)
        float mx0 = -INFINITY, mx1 = -INFINITY;
#pragma unroll
        for (int nf = 0; nf < 8; ++nf) {
            mx0 = fmaxf(mx0, fmaxf(sc[nf][0], sc[nf][1]));
            mx1 = fmaxf(mx1, fmaxf(sc[nf][2], sc[nf][3]));
        }
        mx0 = fmaxf(mx0, __shfl_xor_sync(0xffffffffu, mx0, 1));
        mx0 = fmaxf(mx0, __shfl_xor_sync(0xffffffffu, mx0, 2));
        mx1 = fmaxf(mx1, __shfl_xor_sync(0xffffffffu, mx1, 1));
        mx1 = fmaxf(mx1, __shfl_xor_sync(0xffffffffu, mx1, 2));

        const float mn0 = fmaxf(mrow0, mx0);
        const float mn1 = fmaxf(mrow1, mx1);
        const float corr0 = __expf(mrow0 - mn0);
        const float corr1 = __expf(mrow1 - mn1);
        mrow0 = mn0; mrow1 = mn1;

        float ls0 = 0.f, ls1 = 0.f;
#pragma unroll
        for (int nf = 0; nf < 8; ++nf) {
            sc[nf][0] = __expf(sc[nf][0] - mn0); ls0 += sc[nf][0];
            sc[nf][1] = __expf(sc[nf][1] - mn0); ls0 += sc[nf][1];
            sc[nf][2] = __expf(sc[nf][2] - mn1); ls1 += sc[nf][2];
            sc[nf][3] = __expf(sc[nf][3] - mn1); ls1 += sc[nf][3];
        }
        ls0 += __shfl_xor_sync(0xffffffffu, ls0, 1);
        ls0 += __shfl_xor_sync(0xffffffffu, ls0, 2);
        ls1 += __shfl_xor_sync(0xffffffffu, ls1, 1);
        ls1 += __shfl_xor_sync(0xffffffffu, ls1, 2);
        lrow0 = lrow0 * corr0 + ls0;
        lrow1 = lrow1 * corr1 + ls1;
#pragma unroll
        for (int nf = 0; nf < 8; ++nf) {
            o[nf][0] *= corr0; o[nf][1] *= corr0;
            o[nf][2] *= corr1; o[nf][3] *= corr1;
        }

        __syncthreads();   // all warps done reading KP as K

        // Store P (tf32) into KP; each warp only touches its own 16 rows.
#pragma unroll
        for (int nf = 0; nf < 8; ++nf) {
            uint2 uA, uB;
            uA.x = f2tf(sc[nf][0]); uA.y = f2tf(sc[nf][1]);
            uB.x = f2tf(sc[nf][2]); uB.y = f2tf(sc[nf][3]);
            *(uint2*)&KP[(wr + g) * SV + nf * 8 + 2 * t] = uA;
            *(uint2*)&KP[(wr + g + 8) * SV + nf * 8 + 2 * t] = uB;
        }
        __syncwarp();

        // O += P @ V
#pragma unroll
        for (int kk = 0; kk < 8; ++kk) {
            uint32_t p0 = KP[(wr + g) * SV + kk * 8 + t];
            uint32_t p1 = KP[(wr + g + 8) * SV + kk * 8 + t];
            uint32_t p2 = KP[(wr + g) * SV + kk * 8 + t + 4];
            uint32_t p3 = KP[(wr + g + 8) * SV + kk * 8 + t + 4];
#pragma unroll
            for (int nf = 0; nf < 8; ++nf) {
                uint32_t b0 = Vs[(kk * 8 + t) * SV + nf * 8 + g];
                uint32_t b1 = Vs[(kk * 8 + t + 4) * SV + nf * 8 + g];
                mma_tf32(o[nf], p0, p1, p2, p3, b0, b1);
            }
        }
        __syncthreads();   // before next tile overwrites KP/Vs
    }

    // Epilogue: normalize, write to g_ao[s] in [B, L, H*D]
    const int bb = bh >> 3;
    const int h  = bh & 7;
    const float inv0 = 1.f / lrow0;
    const float inv1 = 1.f / lrow1;
    const int rowA = q0 + wr + g;
    const int rowB = rowA + 8;
    float* __restrict__ ao = &g_ao[s][0];
#pragma unroll
    for (int nf = 0; nf < 8; ++nf) {
        const int col = h * DD + nf * 8 + 2 * t;
        float2 vA = make_float2(o[nf][0] * inv0, o[nf][1] * inv0);
        float2 vB = make_float2(o[nf][2] * inv1, o[nf][3] * inv1);
        *(float2*)&ao[(size_t)(bb * LL + rowA) * CC + col] = vA;
        *(float2*)&ao[(size_t)(bb * LL + rowB) * CC + col] = vB;
    }
}

// ---------------------------------------------------------------------------
extern "C" void kernel_launch(void* const* d_in, const int* in_sizes, int n_in,
                              void* d_out, int out_size)
{
    const float* x1    = (const float*)d_in[0];
    const float* x2    = (const float*)d_in[1];
    const float* qkv_w = (const float*)d_in[2];
    const float* qkv_b = (const float*)d_in[3];
    const float* out_w = (const float*)d_in[4];
    const float* out_b = (const float*)d_in[5];
    float* out = (float*)d_out;

    // Stage 1: QKV projections (both inputs)
    qkv_mma<<<dim3(1536 / 128, BL / 128, 2), 256>>>(x1, x2, qkv_w, qkv_b);

    // Stage 2: cross attention (both directions)
    attn_mma<<<dim3(LL / 64, Bb * HH, 2), 128>>>();

    // Stage 3: output projection -> d_out (out1 then out2)
    proj_mma<<<dim3(CC / 128, 2 * BL / 128), 256>>>(out_w, out_b, out);
}